// round 2
// baseline (speedup 1.0000x reference)
#include <cuda_runtime.h>
#include <math.h>
#include <stdint.h>

#define Bb 4
#define Ll 1024
#define Ee 1024
#define Hh 16
#define DHh 64
#define TOPKk 32

typedef unsigned long long ull;

// -------- scratch (no allocs allowed) --------
__device__ float g_q [Bb*Ll*Ee];
__device__ float g_k [Bb*Ll*Ee];
__device__ float g_v [Bb*Ll*Ee];
__device__ float g_ao[Bb*Ll*Ee];

// ---- packed fp32x2 helpers (bit-identical to 2x fmaf) ----
__device__ __forceinline__ ull pack2(float x) {
    ull r;
    asm("mov.b64 %0, {%1, %1};" : "=l"(r) : "f"(x));
    return r;
}
__device__ __forceinline__ void ffma2(ull& d, ull a, ull b) {
    asm("fma.rn.f32x2 %0, %1, %2, %0;" : "+l"(d) : "l"(a), "l"(b));
}
__device__ __forceinline__ void unpack2(float& lo, float& hi, ull v) {
    asm("mov.b64 {%0, %1}, %2;" : "=f"(lo), "=f"(hi) : "l"(v));
}

// ============================================================
// GEMM: out[M,N] = X[M,K] @ W[N,K]^T + bias[N]   (fp32, FFMA2)
// 128x128 block tile, BK=16, 256 threads, 8x8 microtile.
// Per-output accumulation: ascending k into one register, then +bias
// (bit-identical to round-1 kernel).
// ============================================================
#define GBM 128
#define GBN 128
#define GBK 16

__global__ __launch_bounds__(256, 2) void gemm_nt_bias(
    const float* __restrict__ X, const float* __restrict__ W,
    const float* __restrict__ bias, float* __restrict__ out,
    int M, int N, int K)
{
    __shared__ float As[GBK][GBM];
    __shared__ float Bs[GBK][GBN];

    const int tid = threadIdx.x;
    const int bm = blockIdx.y * GBM;
    const int bn = blockIdx.x * GBN;

    const int tr = (tid / 16) * 8;
    const int tc = (tid % 16) * 8;

    const int arow  = tid >> 2;     // 0..63
    const int acol4 = tid & 3;      // float4 slot in 16-wide row

    ull acc2[8][4];
    #pragma unroll
    for (int i = 0; i < 8; i++)
        #pragma unroll
        for (int j = 0; j < 4; j++) acc2[i][j] = 0ull;

    for (int k0 = 0; k0 < K; k0 += GBK) {
        #pragma unroll
        for (int r = 0; r < 2; r++) {
            int row = arow + r * 64;
            float4 v = *(const float4*)(X + (size_t)(bm + row) * K + k0 + acol4 * 4);
            As[acol4*4+0][row] = v.x;
            As[acol4*4+1][row] = v.y;
            As[acol4*4+2][row] = v.z;
            As[acol4*4+3][row] = v.w;
        }
        #pragma unroll
        for (int r = 0; r < 2; r++) {
            int row = arow + r * 64;
            float4 v = *(const float4*)(W + (size_t)(bn + row) * K + k0 + acol4 * 4);
            Bs[acol4*4+0][row] = v.x;
            Bs[acol4*4+1][row] = v.y;
            Bs[acol4*4+2][row] = v.z;
            Bs[acol4*4+3][row] = v.w;
        }
        __syncthreads();

        #pragma unroll
        for (int k = 0; k < GBK; k++) {
            float ra[8];
            *(float4*)&ra[0] = *(const float4*)&As[k][tr];
            *(float4*)&ra[4] = *(const float4*)&As[k][tr + 4];
            ull rb2[4];
            const ull* b64 = (const ull*)&Bs[k][tc];
            #pragma unroll
            for (int j = 0; j < 4; j++) rb2[j] = b64[j];
            #pragma unroll
            for (int i = 0; i < 8; i++) {
                ull a2 = pack2(ra[i]);
                #pragma unroll
                for (int j = 0; j < 4; j++)
                    ffma2(acc2[i][j], a2, rb2[j]);
            }
        }
        __syncthreads();
    }

    #pragma unroll
    for (int i = 0; i < 8; i++) {
        #pragma unroll
        for (int j = 0; j < 4; j++) {
            float lo, hi;
            unpack2(lo, hi, acc2[i][j]);
            size_t base = (size_t)(bm + tr + i) * N + bn + tc + j * 2;
            out[base]     = lo + bias[bn + tc + j * 2];
            out[base + 1] = hi + bias[bn + tc + j * 2 + 1];
        }
    }
}

// ============================================================
// Attention: per block = (b, h, 128-query tile).
//   - score GEMM 128q x 64k per key tile (FFMA2 microtile 8x8)
//   - per-query running top-32 (value + index) in smem
//   - warp-per-query softmax + sparse V gather epilogue
// ============================================================
#define ATT_QT 128
#define ATT_KT 64
#define ATT_THREADS 128

#define SM_QT   0
#define SM_KT   (SM_QT + 64*128)
#define SM_S    (SM_KT + 64*64)
#define SM_TV   (SM_S  + 128*65)
#define SM_TI   (SM_TV + 128*33)
#define ATT_SMEM_FLOATS (SM_TI + 128*33)

__global__ __launch_bounds__(ATT_THREADS) void attn_topk_kernel(
    const float* __restrict__ gq, const float* __restrict__ gk,
    const float* __restrict__ gv, float* __restrict__ gao)
{
    extern __shared__ float sm[];
    float* sQt = sm + SM_QT;
    float* sKt = sm + SM_KT;
    float* sS  = sm + SM_S;
    float* sTV = sm + SM_TV;
    int*   sTI = (int*)(sm + SM_TI);

    const int tid = threadIdx.x;
    const int bh  = blockIdx.y;          // 0..63
    const int b   = bh / Hh;
    const int h   = bh % Hh;
    const int l0  = blockIdx.x * ATT_QT; // query tile start

    // load 128 queries x 64 dims, transposed into sQt[d][q]
    for (int idx = tid; idx < ATT_QT * DHh; idx += ATT_THREADS) {
        int qq = idx >> 6;
        int d  = idx & 63;
        sQt[d * ATT_QT + qq] = gq[((size_t)(b * Ll + l0 + qq)) * Ee + h * DHh + d];
    }

    // init per-query top-k
    #pragma unroll
    for (int j = 0; j < TOPKk; j++) {
        sTV[tid * 33 + j] = -INFINITY;
        sTI[tid * 33 + j] = 0;
    }
    float curMin = -INFINITY;
    int   curPos = 0;

    const int ty = tid >> 3;  // 0..15  (query group of 8)
    const int tx = tid & 7;   // 0..7   (key group of 8)

    for (int kt = 0; kt < Ll / ATT_KT; kt++) {
        // load key tile transposed: sKt[d][kk]
        for (int idx = tid; idx < ATT_KT * DHh; idx += ATT_THREADS) {
            int kk = idx >> 6;
            int d  = idx & 63;
            sKt[d * ATT_KT + kk] = gk[((size_t)(b * Ll + kt * ATT_KT + kk)) * Ee + h * DHh + d];
        }
        __syncthreads();

        // 128x64 score tile, 8x8 per thread via FFMA2
        ull acc2[8][4];
        #pragma unroll
        for (int i = 0; i < 8; i++)
            #pragma unroll
            for (int j = 0; j < 4; j++) acc2[i][j] = 0ull;

        #pragma unroll 8
        for (int d = 0; d < DHh; d++) {
            float ra[8];
            *(float4*)&ra[0] = *(const float4*)&sQt[d * ATT_QT + ty * 8];
            *(float4*)&ra[4] = *(const float4*)&sQt[d * ATT_QT + ty * 8 + 4];
            ull rb2[4];
            const ull* b64 = (const ull*)&sKt[d * ATT_KT + tx * 8];
            #pragma unroll
            for (int j = 0; j < 4; j++) rb2[j] = b64[j];
            #pragma unroll
            for (int i = 0; i < 8; i++) {
                ull a2 = pack2(ra[i]);
                #pragma unroll
                for (int j = 0; j < 4; j++)
                    ffma2(acc2[i][j], a2, rb2[j]);
            }
        }
        #pragma unroll
        for (int i = 0; i < 8; i++)
            #pragma unroll
            for (int j = 0; j < 4; j++) {
                float lo, hi;
                unpack2(lo, hi, acc2[i][j]);
                sS[(ty * 8 + i) * 65 + tx * 8 + j * 2]     = lo * 0.125f;
                sS[(ty * 8 + i) * 65 + tx * 8 + j * 2 + 1] = hi * 0.125f;
            }
        __syncthreads();

        // per-thread top-32 update over this tile's 64 scores (thread <-> query)
        #pragma unroll 1
        for (int kk = 0; kk < ATT_KT; kk++) {
            float s = sS[tid * 65 + kk];
            if (s > curMin) {
                sTV[tid * 33 + curPos] = s;
                sTI[tid * 33 + curPos] = kt * ATT_KT + kk;
                float mn = sTV[tid * 33];
                int   mp = 0;
                #pragma unroll
                for (int j = 1; j < TOPKk; j++) {
                    float v = sTV[tid * 33 + j];
                    if (v < mn) { mn = v; mp = j; }
                }
                curMin = mn; curPos = mp;
            }
        }
        __syncthreads();
    }

    // epilogue: warp per query — softmax over 32 + sparse V gather
    const int warp = tid >> 5;
    const int lane = tid & 31;
    for (int qi = warp; qi < ATT_QT; qi += 4) {
        float v  = sTV[qi * 33 + lane];
        int   ki = sTI[qi * 33 + lane];

        float mx = v;
        #pragma unroll
        for (int o = 16; o; o >>= 1) mx = fmaxf(mx, __shfl_xor_sync(0xffffffffu, mx, o));
        float e = expf(v - mx);
        float se = e;
        #pragma unroll
        for (int o = 16; o; o >>= 1) se += __shfl_xor_sync(0xffffffffu, se, o);
        float w = e / se;

        float a0 = 0.f, a1 = 0.f;
        #pragma unroll
        for (int j = 0; j < TOPKk; j++) {
            float wj = __shfl_sync(0xffffffffu, w, j);
            int   kj = __shfl_sync(0xffffffffu, ki, j);
            const float* vr = gv + ((size_t)(b * Ll + kj)) * Ee + h * DHh;
            a0 = fmaf(wj, vr[lane],      a0);
            a1 = fmaf(wj, vr[lane + 32], a1);
        }
        float* op = gao + ((size_t)(b * Ll + l0 + qi)) * Ee + h * DHh;
        op[lane]      = a0;
        op[lane + 32] = a1;
    }
}

// ============================================================
extern "C" void kernel_launch(void* const* d_in, const int* in_sizes, int n_in,
                              void* d_out, int out_size)
{
    const float* Q  = (const float*)d_in[0];
    const float* K_ = (const float*)d_in[1];
    const float* V  = (const float*)d_in[2];
    const float* Wq = (const float*)d_in[3];
    const float* bq = (const float*)d_in[4];
    const float* Wk = (const float*)d_in[5];
    const float* bk = (const float*)d_in[6];
    const float* Wv = (const float*)d_in[7];
    const float* bv = (const float*)d_in[8];
    const float* Wo = (const float*)d_in[9];
    const float* bo = (const float*)d_in[10];
    float* out = (float*)d_out;

    float *gq, *gk, *gv, *gao;
    cudaGetSymbolAddress((void**)&gq,  g_q);
    cudaGetSymbolAddress((void**)&gk,  g_k);
    cudaGetSymbolAddress((void**)&gv,  g_v);
    cudaGetSymbolAddress((void**)&gao, g_ao);

    const int M = Bb * Ll;   // 4096
    const int N = Ee;        // 1024
    const int K = Ee;        // 1024

    dim3 gblock(256);
    dim3 ggrid(N / GBN, M / GBM);  // (8, 32)

    // projections
    gemm_nt_bias<<<ggrid, gblock>>>(Q,  Wq, bq, gq, M, N, K);
    gemm_nt_bias<<<ggrid, gblock>>>(K_, Wk, bk, gk, M, N, K);
    gemm_nt_bias<<<ggrid, gblock>>>(V,  Wv, bv, gv, M, N, K);

    // sparse top-k attention
    size_t attSmem = ATT_SMEM_FLOATS * sizeof(float);  // ~116 KB
    cudaFuncSetAttribute(attn_topk_kernel,
                         cudaFuncAttributeMaxDynamicSharedMemorySize, (int)attSmem);
    dim3 agrid(Ll / ATT_QT, Bb * Hh);  // (8, 64)
    attn_topk_kernel<<<agrid, ATT_THREADS, attSmem>>>(gq, gk, gv, gao);

    // output projection
    gemm_nt_bias<<<ggrid, gblock>>>(gao, Wo, bo, out, M, N, K);
}

// round 4
// speedup vs baseline: 1.1199x; 1.1199x over previous
#include <cuda_runtime.h>
#include <cuda_bf16.h>
#include <math.h>
#include <stdint.h>

#define Bb 4
#define Ll 1024
#define Ee 1024
#define Hh 16
#define DHh 64
#define TOPKk 32

// -------- scratch (no allocs allowed) --------
__device__ float g_q [Bb*Ll*Ee];
__device__ float g_k [Bb*Ll*Ee];
__device__ float g_v [Bb*Ll*Ee];
__device__ float g_ao[Bb*Ll*Ee];

// bf16x2 split planes (reused for V-input/gao and Wv/Wo)
__device__ __nv_bfloat16 g_xs1[Bb*Ll*Ee];
__device__ __nv_bfloat16 g_xs2[Bb*Ll*Ee];
__device__ __nv_bfloat16 g_ws1[Ee*Ee];
__device__ __nv_bfloat16 g_ws2[Ee*Ee];

// ============================================================
// Scalar fp32 GEMM (bit-identical to round-1): used for Wq, Wk.
// out[M,N] = X[M,K] @ W[N,K]^T + bias[N]
// ============================================================
#define GBM 128
#define GBN 128
#define GBK 16

__global__ __launch_bounds__(256) void gemm_nt_bias(
    const float* __restrict__ X, const float* __restrict__ W,
    const float* __restrict__ bias, float* __restrict__ out,
    int M, int N, int K)
{
    __shared__ float As[GBK][GBM];
    __shared__ float Bs[GBK][GBN];

    const int tid = threadIdx.x;
    const int bm = blockIdx.y * GBM;
    const int bn = blockIdx.x * GBN;

    const int tr = (tid / 16) * 8;
    const int tc = (tid % 16) * 8;

    const int arow  = tid >> 2;
    const int acol4 = tid & 3;

    float acc[8][8] = {};

    for (int k0 = 0; k0 < K; k0 += GBK) {
        #pragma unroll
        for (int r = 0; r < 2; r++) {
            int row = arow + r * 64;
            float4 v = *(const float4*)(X + (size_t)(bm + row) * K + k0 + acol4 * 4);
            As[acol4*4+0][row] = v.x;
            As[acol4*4+1][row] = v.y;
            As[acol4*4+2][row] = v.z;
            As[acol4*4+3][row] = v.w;
        }
        #pragma unroll
        for (int r = 0; r < 2; r++) {
            int row = arow + r * 64;
            float4 v = *(const float4*)(W + (size_t)(bn + row) * K + k0 + acol4 * 4);
            Bs[acol4*4+0][row] = v.x;
            Bs[acol4*4+1][row] = v.y;
            Bs[acol4*4+2][row] = v.z;
            Bs[acol4*4+3][row] = v.w;
        }
        __syncthreads();

        #pragma unroll
        for (int k = 0; k < GBK; k++) {
            float ra[8], rb[8];
            #pragma unroll
            for (int i = 0; i < 8; i++) ra[i] = As[k][tr + i];
            #pragma unroll
            for (int j = 0; j < 8; j++) rb[j] = Bs[k][tc + j];
            #pragma unroll
            for (int i = 0; i < 8; i++)
                #pragma unroll
                for (int j = 0; j < 8; j++)
                    acc[i][j] = fmaf(ra[i], rb[j], acc[i][j]);
        }
        __syncthreads();
    }

    #pragma unroll
    for (int i = 0; i < 8; i++) {
        #pragma unroll
        for (int j = 0; j < 8; j++) {
            out[(size_t)(bm + tr + i) * N + bn + tc + j] = acc[i][j] + bias[bn + tc + j];
        }
    }
}

// ============================================================
// bf16x2 split: x = b1 + b2  (b2 captures next 8 mantissa bits)
// ============================================================
__global__ void split2_kernel(const float* __restrict__ src,
                              __nv_bfloat16* __restrict__ p1,
                              __nv_bfloat16* __restrict__ p2, int n)
{
    int i = blockIdx.x * blockDim.x + threadIdx.x;
    if (i >= n) return;
    float x = src[i];
    __nv_bfloat16 b1 = __float2bfloat16_rn(x);
    float r1 = x - __bfloat162float(b1);
    p1[i] = b1;
    p2[i] = __float2bfloat16_rn(r1);
}

// ============================================================
// Tensor-core GEMM via mma.sync (baseline PTX, not arch-gated):
// out[4096,1024] = X @ W^T + bias, fp32-accurate via bf16x2 split,
// 3 terms: A1*B1 + A1*B2 + A2*B1  (B2*A2 ~ 2^-16, dropped).
// Block tile 128x128, k-chunk 32, 8 warps (4m x 2n), warp tile 32x64.
// ============================================================
#define TK 1024
#define TN 1024

__device__ __forceinline__ void mma16816(
    float& d0, float& d1, float& d2, float& d3,
    uint32_t a0, uint32_t a1, uint32_t a2, uint32_t a3,
    uint32_t b0, uint32_t b1)
{
    asm volatile(
        "mma.sync.aligned.m16n8k16.row.col.f32.bf16.bf16.f32 "
        "{%0,%1,%2,%3}, {%4,%5,%6,%7}, {%8,%9}, {%0,%1,%2,%3};"
        : "+f"(d0), "+f"(d1), "+f"(d2), "+f"(d3)
        : "r"(a0), "r"(a1), "r"(a2), "r"(a3), "r"(b0), "r"(b1));
}

#define SROW 40   // padded smem row stride (bf16) -> conflict-free frag loads

__global__ __launch_bounds__(256) void gemm_bf16x2_mma(
    const __nv_bfloat16* __restrict__ A1, const __nv_bfloat16* __restrict__ A2,
    const __nv_bfloat16* __restrict__ B1, const __nv_bfloat16* __restrict__ B2,
    const float* __restrict__ bias, float* __restrict__ out)
{
    __shared__ __nv_bfloat16 sA[2][128][SROW];
    __shared__ __nv_bfloat16 sB[2][128][SROW];

    const int tid = threadIdx.x;
    const int wid = tid >> 5;
    const int lane = tid & 31;
    const int g  = lane >> 2;     // 0..7
    const int tg = lane & 3;      // 0..3

    const int bm = blockIdx.y * 128;
    const int bn = blockIdx.x * 128;
    const int wm = (wid >> 1) * 32;  // warp m offset in tile
    const int wn = (wid & 1) * 64;   // warp n offset in tile

    const __nv_bfloat16* Ap[2] = {A1, A2};
    const __nv_bfloat16* Bp[2] = {B1, B2};

    float acc[2][8][4] = {};   // [mt][nt][c0..c3]

    for (int kc = 0; kc < TK / 32; kc++) {
        const int k0 = kc * 32;
        // cooperative load: 2 planes x 128 rows x 32 bf16, as uint4 (8 bf16)
        #pragma unroll
        for (int it = 0; it < 4; it++) {
            int idx = tid + it * 256;        // 0..1023
            int p   = idx >> 9;              // plane
            int rem = idx & 511;
            int row = rem >> 2;
            int seg = rem & 3;
            *(uint4*)&sA[p][row][seg * 8] =
                *(const uint4*)(Ap[p] + (size_t)(bm + row) * TK + k0 + seg * 8);
            *(uint4*)&sB[p][row][seg * 8] =
                *(const uint4*)(Bp[p] + (size_t)(bn + row) * TK + k0 + seg * 8);
        }
        __syncthreads();

        #pragma unroll
        for (int ks = 0; ks < 2; ks++) {     // two k16 steps per chunk
            const int kb = ks * 16;
            // A fragments: [plane][mt][4 regs]
            uint32_t af[2][2][4];
            #pragma unroll
            for (int p = 0; p < 2; p++)
                #pragma unroll
                for (int mt = 0; mt < 2; mt++) {
                    int r0 = wm + mt * 16 + g;
                    af[p][mt][0] = *(const uint32_t*)&sA[p][r0    ][kb + tg * 2];
                    af[p][mt][1] = *(const uint32_t*)&sA[p][r0 + 8][kb + tg * 2];
                    af[p][mt][2] = *(const uint32_t*)&sA[p][r0    ][kb + 8 + tg * 2];
                    af[p][mt][3] = *(const uint32_t*)&sA[p][r0 + 8][kb + 8 + tg * 2];
                }
            // B fragments: [plane][nt][2 regs]
            uint32_t bf[2][8][2];
            #pragma unroll
            for (int p = 0; p < 2; p++)
                #pragma unroll
                for (int nt = 0; nt < 8; nt++) {
                    int nr = wn + nt * 8 + g;
                    bf[p][nt][0] = *(const uint32_t*)&sB[p][nr][kb + tg * 2];
                    bf[p][nt][1] = *(const uint32_t*)&sB[p][nr][kb + 8 + tg * 2];
                }
            // 3 terms: (A1,B1), (A1,B2), (A2,B1)
            #pragma unroll
            for (int mt = 0; mt < 2; mt++)
                #pragma unroll
                for (int nt = 0; nt < 8; nt++) {
                    mma16816(acc[mt][nt][0], acc[mt][nt][1], acc[mt][nt][2], acc[mt][nt][3],
                             af[0][mt][0], af[0][mt][1], af[0][mt][2], af[0][mt][3],
                             bf[0][nt][0], bf[0][nt][1]);
                    mma16816(acc[mt][nt][0], acc[mt][nt][1], acc[mt][nt][2], acc[mt][nt][3],
                             af[0][mt][0], af[0][mt][1], af[0][mt][2], af[0][mt][3],
                             bf[1][nt][0], bf[1][nt][1]);
                    mma16816(acc[mt][nt][0], acc[mt][nt][1], acc[mt][nt][2], acc[mt][nt][3],
                             af[1][mt][0], af[1][mt][1], af[1][mt][2], af[1][mt][3],
                             bf[0][nt][0], bf[0][nt][1]);
                }
        }
        __syncthreads();
    }

    // epilogue: D[g][2tg], D[g][2tg+1], D[g+8][2tg], D[g+8][2tg+1] per 16x8 tile
    #pragma unroll
    for (int mt = 0; mt < 2; mt++) {
        #pragma unroll
        for (int nt = 0; nt < 8; nt++) {
            int m0 = bm + wm + mt * 16 + g;
            int n0 = bn + wn + nt * 8 + tg * 2;
            float b0 = bias[n0], b1 = bias[n0 + 1];
            float2 lo = make_float2(acc[mt][nt][0] + b0, acc[mt][nt][1] + b1);
            float2 hi = make_float2(acc[mt][nt][2] + b0, acc[mt][nt][3] + b1);
            *(float2*)(out + (size_t)m0 * TN + n0)       = lo;
            *(float2*)(out + (size_t)(m0 + 8) * TN + n0) = hi;
        }
    }
}

// ============================================================
// Attention (bit-identical to round-1)
// ============================================================
#define ATT_QT 128
#define ATT_KT 64
#define ATT_THREADS 128

#define SM_QT   0
#define SM_KT   (SM_QT + 64*128)
#define SM_S    (SM_KT + 64*64)
#define SM_TV   (SM_S  + 128*65)
#define SM_TI   (SM_TV + 128*33)
#define ATT_SMEM_FLOATS (SM_TI + 128*33)

__global__ __launch_bounds__(ATT_THREADS) void attn_topk_kernel(
    const float* __restrict__ gq, const float* __restrict__ gk,
    const float* __restrict__ gv, float* __restrict__ gao)
{
    extern __shared__ float sm[];
    float* sQt = sm + SM_QT;
    float* sKt = sm + SM_KT;
    float* sS  = sm + SM_S;
    float* sTV = sm + SM_TV;
    int*   sTI = (int*)(sm + SM_TI);

    const int tid = threadIdx.x;
    const int bh  = blockIdx.y;
    const int b   = bh / Hh;
    const int h   = bh % Hh;
    const int l0  = blockIdx.x * ATT_QT;

    for (int idx = tid; idx < ATT_QT * DHh; idx += ATT_THREADS) {
        int qq = idx >> 6;
        int d  = idx & 63;
        sQt[d * ATT_QT + qq] = gq[((size_t)(b * Ll + l0 + qq)) * Ee + h * DHh + d];
    }

    #pragma unroll
    for (int j = 0; j < TOPKk; j++) {
        sTV[tid * 33 + j] = -INFINITY;
        sTI[tid * 33 + j] = 0;
    }
    float curMin = -INFINITY;
    int   curPos = 0;

    const int ty = tid >> 3;
    const int tx = tid & 7;

    for (int kt = 0; kt < Ll / ATT_KT; kt++) {
        for (int idx = tid; idx < ATT_KT * DHh; idx += ATT_THREADS) {
            int kk = idx >> 6;
            int d  = idx & 63;
            sKt[d * ATT_KT + kk] = gk[((size_t)(b * Ll + kt * ATT_KT + kk)) * Ee + h * DHh + d];
        }
        __syncthreads();

        float acc[8][8] = {};
        #pragma unroll 8
        for (int d = 0; d < DHh; d++) {
            float ra[8], rb[8];
            #pragma unroll
            for (int i = 0; i < 8; i++) ra[i] = sQt[d * ATT_QT + ty * 8 + i];
            #pragma unroll
            for (int j = 0; j < 8; j++) rb[j] = sKt[d * ATT_KT + tx * 8 + j];
            #pragma unroll
            for (int i = 0; i < 8; i++)
                #pragma unroll
                for (int j = 0; j < 8; j++)
                    acc[i][j] = fmaf(ra[i], rb[j], acc[i][j]);
        }
        #pragma unroll
        for (int i = 0; i < 8; i++)
            #pragma unroll
            for (int j = 0; j < 8; j++)
                sS[(ty * 8 + i) * 65 + tx * 8 + j] = acc[i][j] * 0.125f;
        __syncthreads();

        #pragma unroll 1
        for (int kk = 0; kk < ATT_KT; kk++) {
            float s = sS[tid * 65 + kk];
            if (s > curMin) {
                sTV[tid * 33 + curPos] = s;
                sTI[tid * 33 + curPos] = kt * ATT_KT + kk;
                float mn = sTV[tid * 33];
                int   mp = 0;
                #pragma unroll
                for (int j = 1; j < TOPKk; j++) {
                    float v = sTV[tid * 33 + j];
                    if (v < mn) { mn = v; mp = j; }
                }
                curMin = mn; curPos = mp;
            }
        }
        __syncthreads();
    }

    const int warp = tid >> 5;
    const int lane = tid & 31;
    for (int qi = warp; qi < ATT_QT; qi += 4) {
        float v  = sTV[qi * 33 + lane];
        int   ki = sTI[qi * 33 + lane];

        float mx = v;
        #pragma unroll
        for (int o = 16; o; o >>= 1) mx = fmaxf(mx, __shfl_xor_sync(0xffffffffu, mx, o));
        float e = expf(v - mx);
        float se = e;
        #pragma unroll
        for (int o = 16; o; o >>= 1) se += __shfl_xor_sync(0xffffffffu, se, o);
        float w = e / se;

        float a0 = 0.f, a1 = 0.f;
        #pragma unroll
        for (int j = 0; j < TOPKk; j++) {
            float wj = __shfl_sync(0xffffffffu, w, j);
            int   kj = __shfl_sync(0xffffffffu, ki, j);
            const float* vr = gv + ((size_t)(b * Ll + kj)) * Ee + h * DHh;
            a0 = fmaf(wj, vr[lane],      a0);
            a1 = fmaf(wj, vr[lane + 32], a1);
        }
        float* op = gao + ((size_t)(b * Ll + l0 + qi)) * Ee + h * DHh;
        op[lane]      = a0;
        op[lane + 32] = a1;
    }
}

// ============================================================
extern "C" void kernel_launch(void* const* d_in, const int* in_sizes, int n_in,
                              void* d_out, int out_size)
{
    const float* Q  = (const float*)d_in[0];
    const float* K_ = (const float*)d_in[1];
    const float* V  = (const float*)d_in[2];
    const float* Wq = (const float*)d_in[3];
    const float* bq = (const float*)d_in[4];
    const float* Wk = (const float*)d_in[5];
    const float* bk = (const float*)d_in[6];
    const float* Wv = (const float*)d_in[7];
    const float* bv = (const float*)d_in[8];
    const float* Wo = (const float*)d_in[9];
    const float* bo = (const float*)d_in[10];
    float* out = (float*)d_out;

    float *gq, *gk, *gv, *gao;
    cudaGetSymbolAddress((void**)&gq,  g_q);
    cudaGetSymbolAddress((void**)&gk,  g_k);
    cudaGetSymbolAddress((void**)&gv,  g_v);
    cudaGetSymbolAddress((void**)&gao, g_ao);
    __nv_bfloat16 *xs1, *xs2, *ws1, *ws2;
    cudaGetSymbolAddress((void**)&xs1, g_xs1);
    cudaGetSymbolAddress((void**)&xs2, g_xs2);
    cudaGetSymbolAddress((void**)&ws1, g_ws1);
    cudaGetSymbolAddress((void**)&ws2, g_ws2);

    const int M = Bb * Ll;   // 4096
    const int N = Ee;        // 1024
    const int K = Ee;        // 1024

    dim3 gblock(256);
    dim3 ggrid(N / GBN, M / GBM);  // (8, 32)

    // q, k projections: scalar fp32 (bit-identical -> preserves top-k draw)
    gemm_nt_bias<<<ggrid, gblock>>>(Q,  Wq, bq, gq, M, N, K);
    gemm_nt_bias<<<ggrid, gblock>>>(K_, Wk, bk, gk, M, N, K);

    // v projection: tensor-core bf16x2 (selection-free path)
    split2_kernel<<<(M*K + 255)/256, 256>>>(V,  xs1, xs2, M*K);
    split2_kernel<<<(N*K + 255)/256, 256>>>(Wv, ws1, ws2, N*K);
    dim3 tgrid(N / 128, M / 128);  // (8, 32)
    gemm_bf16x2_mma<<<tgrid, 256>>>(xs1, xs2, ws1, ws2, bv, gv);

    // sparse top-k attention (bit-identical)
    size_t attSmem = ATT_SMEM_FLOATS * sizeof(float);
    cudaFuncSetAttribute(attn_topk_kernel,
                         cudaFuncAttributeMaxDynamicSharedMemorySize, (int)attSmem);
    dim3 agrid(Ll / ATT_QT, Bb * Hh);  // (8, 64)
    attn_topk_kernel<<<agrid, ATT_THREADS, attSmem>>>(gq, gk, gv, gao);

    // output projection: tensor-core bf16x2
    split2_kernel<<<(M*K + 255)/256, 256>>>(gao, xs1, xs2, M*K);
    split2_kernel<<<(N*K + 255)/256, 256>>>(Wo,  ws1, ws2, N*K);
    gemm_bf16x2_mma<<<tgrid, 256>>>(xs1, xs2, ws1, ws2, bo, out);
}

// round 5
// speedup vs baseline: 1.1777x; 1.0516x over previous
#include <cuda_runtime.h>
#include <cuda_bf16.h>
#include <math.h>
#include <stdint.h>

#define Bb 4
#define Ll 1024
#define Ee 1024
#define Hh 16
#define DHh 64
#define TOPKk 32

// -------- scratch (no allocs allowed) --------
__device__ float g_q [Bb*Ll*Ee];
__device__ float g_k [Bb*Ll*Ee];
__device__ float g_v [Bb*Ll*Ee];
__device__ float g_ao[Bb*Ll*Ee];

// bf16x2 split planes (reused for V-input/gao and Wv/Wo)
__device__ __nv_bfloat16 g_xs1[Bb*Ll*Ee];
__device__ __nv_bfloat16 g_xs2[Bb*Ll*Ee];
__device__ __nv_bfloat16 g_ws1[Ee*Ee];
__device__ __nv_bfloat16 g_ws2[Ee*Ee];

// ============================================================
// Scalar fp32 GEMM (bit-identical to round-1): used for Wq, Wk.
// ============================================================
#define GBM 128
#define GBN 128
#define GBK 16

__global__ __launch_bounds__(256) void gemm_nt_bias(
    const float* __restrict__ X, const float* __restrict__ W,
    const float* __restrict__ bias, float* __restrict__ out,
    int M, int N, int K)
{
    __shared__ float As[GBK][GBM];
    __shared__ float Bs[GBK][GBN];

    const int tid = threadIdx.x;
    const int bm = blockIdx.y * GBM;
    const int bn = blockIdx.x * GBN;

    const int tr = (tid / 16) * 8;
    const int tc = (tid % 16) * 8;

    const int arow  = tid >> 2;
    const int acol4 = tid & 3;

    float acc[8][8] = {};

    for (int k0 = 0; k0 < K; k0 += GBK) {
        #pragma unroll
        for (int r = 0; r < 2; r++) {
            int row = arow + r * 64;
            float4 v = *(const float4*)(X + (size_t)(bm + row) * K + k0 + acol4 * 4);
            As[acol4*4+0][row] = v.x;
            As[acol4*4+1][row] = v.y;
            As[acol4*4+2][row] = v.z;
            As[acol4*4+3][row] = v.w;
        }
        #pragma unroll
        for (int r = 0; r < 2; r++) {
            int row = arow + r * 64;
            float4 v = *(const float4*)(W + (size_t)(bn + row) * K + k0 + acol4 * 4);
            Bs[acol4*4+0][row] = v.x;
            Bs[acol4*4+1][row] = v.y;
            Bs[acol4*4+2][row] = v.z;
            Bs[acol4*4+3][row] = v.w;
        }
        __syncthreads();

        #pragma unroll
        for (int k = 0; k < GBK; k++) {
            float ra[8], rb[8];
            #pragma unroll
            for (int i = 0; i < 8; i++) ra[i] = As[k][tr + i];
            #pragma unroll
            for (int j = 0; j < 8; j++) rb[j] = Bs[k][tc + j];
            #pragma unroll
            for (int i = 0; i < 8; i++)
                #pragma unroll
                for (int j = 0; j < 8; j++)
                    acc[i][j] = fmaf(ra[i], rb[j], acc[i][j]);
        }
        __syncthreads();
    }

    #pragma unroll
    for (int i = 0; i < 8; i++) {
        #pragma unroll
        for (int j = 0; j < 8; j++) {
            out[(size_t)(bm + tr + i) * N + bn + tc + j] = acc[i][j] + bias[bn + tc + j];
        }
    }
}

// ============================================================
// bf16x2 split
// ============================================================
__global__ void split2_kernel(const float* __restrict__ src,
                              __nv_bfloat16* __restrict__ p1,
                              __nv_bfloat16* __restrict__ p2, int n)
{
    int i = blockIdx.x * blockDim.x + threadIdx.x;
    if (i >= n) return;
    float x = src[i];
    __nv_bfloat16 b1 = __float2bfloat16_rn(x);
    float r1 = x - __bfloat162float(b1);
    p1[i] = b1;
    p2[i] = __float2bfloat16_rn(r1);
}

// ============================================================
// Tensor-core GEMM via mma.sync with cp.async double buffering.
// out[4096,1024] = X @ W^T + bias (bf16x2 split, 3 terms).
// Block tile 128x128, k-chunk 32, 8 warps (4m x 2n), warp 32x64.
// ============================================================
#define TK 1024
#define TN 1024
#define NCHUNK (TK / 32)
#define SROWB 80                 // padded row stride in BYTES (40 bf16)
#define TILE_B (128 * SROWB)     // 10240 B per (plane, A/B) tile
#define STAGE_B (4 * TILE_B)     // A1,A2,B1,B2 per stage = 40960 B
#define TG_SMEM (2 * STAGE_B)    // 81920 B

__device__ __forceinline__ void mma16816(
    float& d0, float& d1, float& d2, float& d3,
    uint32_t a0, uint32_t a1, uint32_t a2, uint32_t a3,
    uint32_t b0, uint32_t b1)
{
    asm volatile(
        "mma.sync.aligned.m16n8k16.row.col.f32.bf16.bf16.f32 "
        "{%0,%1,%2,%3}, {%4,%5,%6,%7}, {%8,%9}, {%0,%1,%2,%3};"
        : "+f"(d0), "+f"(d1), "+f"(d2), "+f"(d3)
        : "r"(a0), "r"(a1), "r"(a2), "r"(a3), "r"(b0), "r"(b1));
}

__device__ __forceinline__ uint32_t smem_u32(const void* p) {
    uint32_t a;
    asm("{ .reg .u64 t; cvta.to.shared.u64 t, %1; cvt.u32.u64 %0, t; }" : "=r"(a) : "l"(p));
    return a;
}
__device__ __forceinline__ void cp_async16(uint32_t saddr, const void* g) {
    asm volatile("cp.async.cg.shared.global [%0], [%1], 16;" :: "r"(saddr), "l"(g));
}
#define CP_COMMIT() asm volatile("cp.async.commit_group;" ::: "memory")
#define CP_WAIT(n)  asm volatile("cp.async.wait_group %0;" :: "n"(n) : "memory")

__global__ __launch_bounds__(256) void gemm_bf16x2_mma(
    const __nv_bfloat16* __restrict__ A1, const __nv_bfloat16* __restrict__ A2,
    const __nv_bfloat16* __restrict__ B1, const __nv_bfloat16* __restrict__ B2,
    const float* __restrict__ bias, float* __restrict__ out)
{
    extern __shared__ char smem[];
    const uint32_t smem_b = smem_u32(smem);

    const int tid = threadIdx.x;
    const int wid = tid >> 5;
    const int lane = tid & 31;
    const int g  = lane >> 2;
    const int tg = lane & 3;

    const int bm = blockIdx.y * 128;
    const int bn = blockIdx.x * 128;
    const int wm = (wid >> 1) * 32;
    const int wn = (wid & 1) * 64;

    const __nv_bfloat16* gp[4] = {A1, A2, B1, B2};  // [ab*2+p]
    const int gbase[4] = {bm, bm, bn, bn};

    // per-thread cp.async slots: 2048 16B chunks / 256 threads = 8 each
    // chunk c: t = c>>9 (tile 0..3 = A1,A2,B1,B2), rem = c&511, row = rem>>2, seg = rem&3
    float acc[2][8][4] = {};

    for (int kc = 0; kc < NCHUNK + 1; kc++) {
        // issue stage (kc)&1 load for chunk kc (if any)
        if (kc < NCHUNK) {
            const int k0 = kc * 32;
            const uint32_t stage_off = (uint32_t)(kc & 1) * STAGE_B;
            #pragma unroll
            for (int it = 0; it < 8; it++) {
                int c = tid + it * 256;
                int t = c >> 9;
                int rem = c & 511;
                int row = rem >> 2;
                int seg = rem & 3;
                uint32_t sa = smem_b + stage_off + (uint32_t)t * TILE_B
                            + (uint32_t)row * SROWB + (uint32_t)seg * 16;
                const __nv_bfloat16* gsrc = gp[t] + (size_t)(gbase[t] + row) * TK + k0 + seg * 8;
                cp_async16(sa, gsrc);
            }
            CP_COMMIT();
        }
        if (kc == 0) continue;   // nothing to compute yet

        // wait for chunk kc-1 (stage (kc-1)&1)
        if (kc < NCHUNK) { CP_WAIT(1); } else { CP_WAIT(0); }
        __syncthreads();

        const char* st = smem + ((kc - 1) & 1) * STAGE_B;
        const __nv_bfloat16* sA[2] = {(const __nv_bfloat16*)(st),
                                      (const __nv_bfloat16*)(st + TILE_B)};
        const __nv_bfloat16* sB[2] = {(const __nv_bfloat16*)(st + 2 * TILE_B),
                                      (const __nv_bfloat16*)(st + 3 * TILE_B)};

        #pragma unroll
        for (int ks = 0; ks < 2; ks++) {
            const int kb = ks * 16;
            uint32_t af[2][2][4];
            #pragma unroll
            for (int p = 0; p < 2; p++)
                #pragma unroll
                for (int mt = 0; mt < 2; mt++) {
                    int r0 = wm + mt * 16 + g;
                    const char* base = (const char*)sA[p];
                    af[p][mt][0] = *(const uint32_t*)(base + (r0    ) * SROWB + (kb + tg * 2) * 2);
                    af[p][mt][1] = *(const uint32_t*)(base + (r0 + 8) * SROWB + (kb + tg * 2) * 2);
                    af[p][mt][2] = *(const uint32_t*)(base + (r0    ) * SROWB + (kb + 8 + tg * 2) * 2);
                    af[p][mt][3] = *(const uint32_t*)(base + (r0 + 8) * SROWB + (kb + 8 + tg * 2) * 2);
                }
            uint32_t bf[2][8][2];
            #pragma unroll
            for (int p = 0; p < 2; p++)
                #pragma unroll
                for (int nt = 0; nt < 8; nt++) {
                    int nr = wn + nt * 8 + g;
                    const char* base = (const char*)sB[p];
                    bf[p][nt][0] = *(const uint32_t*)(base + nr * SROWB + (kb + tg * 2) * 2);
                    bf[p][nt][1] = *(const uint32_t*)(base + nr * SROWB + (kb + 8 + tg * 2) * 2);
                }
            #pragma unroll
            for (int mt = 0; mt < 2; mt++)
                #pragma unroll
                for (int nt = 0; nt < 8; nt++) {
                    mma16816(acc[mt][nt][0], acc[mt][nt][1], acc[mt][nt][2], acc[mt][nt][3],
                             af[0][mt][0], af[0][mt][1], af[0][mt][2], af[0][mt][3],
                             bf[0][nt][0], bf[0][nt][1]);
                    mma16816(acc[mt][nt][0], acc[mt][nt][1], acc[mt][nt][2], acc[mt][nt][3],
                             af[0][mt][0], af[0][mt][1], af[0][mt][2], af[0][mt][3],
                             bf[1][nt][0], bf[1][nt][1]);
                    mma16816(acc[mt][nt][0], acc[mt][nt][1], acc[mt][nt][2], acc[mt][nt][3],
                             af[1][mt][0], af[1][mt][1], af[1][mt][2], af[1][mt][3],
                             bf[0][nt][0], bf[0][nt][1]);
                }
        }
        __syncthreads();
    }

    #pragma unroll
    for (int mt = 0; mt < 2; mt++) {
        #pragma unroll
        for (int nt = 0; nt < 8; nt++) {
            int m0 = bm + wm + mt * 16 + g;
            int n0 = bn + wn + nt * 8 + tg * 2;
            float b0 = bias[n0], b1 = bias[n0 + 1];
            float2 lo = make_float2(acc[mt][nt][0] + b0, acc[mt][nt][1] + b1);
            float2 hi = make_float2(acc[mt][nt][2] + b0, acc[mt][nt][3] + b1);
            *(float2*)(out + (size_t)m0 * TN + n0)       = lo;
            *(float2*)(out + (size_t)(m0 + 8) * TN + n0) = hi;
        }
    }
}

// ============================================================
// Attention: 256 threads/block. Scores bit-identical (same
// d-ascending fma chain per output); scan/selection/epilogue
// sums identical to round-4 -> gao bit-identical.
// ============================================================
#define ATT_QT 128
#define ATT_KT 64
#define ATT_THREADS 256

#define SM_QT   0
#define SM_KT   (SM_QT + 64*128)
#define SM_S    (SM_KT + 64*64)
#define SM_TV   (SM_S  + 128*65)
#define SM_TI   (SM_TV + 128*33)
#define ATT_SMEM_FLOATS (SM_TI + 128*33)

__global__ __launch_bounds__(ATT_THREADS) void attn_topk_kernel(
    const float* __restrict__ gq, const float* __restrict__ gk,
    const float* __restrict__ gv, float* __restrict__ gao)
{
    extern __shared__ float sm[];
    float* sQt = sm + SM_QT;
    float* sKt = sm + SM_KT;
    float* sS  = sm + SM_S;
    float* sTV = sm + SM_TV;
    int*   sTI = (int*)(sm + SM_TI);

    const int tid = threadIdx.x;
    const int bh  = blockIdx.y;
    const int b   = bh / Hh;
    const int h   = bh % Hh;
    const int l0  = blockIdx.x * ATT_QT;

    for (int idx = tid; idx < ATT_QT * DHh; idx += ATT_THREADS) {
        int qq = idx >> 6;
        int d  = idx & 63;
        sQt[d * ATT_QT + qq] = gq[((size_t)(b * Ll + l0 + qq)) * Ee + h * DHh + d];
    }

    if (tid < 128) {
        #pragma unroll
        for (int j = 0; j < TOPKk; j++) {
            sTV[tid * 33 + j] = -INFINITY;
            sTI[tid * 33 + j] = 0;
        }
    }
    float curMin = -INFINITY;
    int   curPos = 0;

    const int ty = tid >> 3;  // 0..31 (query group of 4)
    const int tx = tid & 7;   // 0..7  (key group of 8)

    for (int kt = 0; kt < Ll / ATT_KT; kt++) {
        for (int idx = tid; idx < ATT_KT * DHh; idx += ATT_THREADS) {
            int kk = idx >> 6;
            int d  = idx & 63;
            sKt[d * ATT_KT + kk] = gk[((size_t)(b * Ll + kt * ATT_KT + kk)) * Ee + h * DHh + d];
        }
        __syncthreads();

        // 128x64 score tile, 4x8 per thread (same per-output fma chain)
        float acc[4][8] = {};
        #pragma unroll 8
        for (int d = 0; d < DHh; d++) {
            float ra[4], rb[8];
            *(float4*)&ra[0] = *(const float4*)&sQt[d * ATT_QT + ty * 4];
            *(float4*)&rb[0] = *(const float4*)&sKt[d * ATT_KT + tx * 8];
            *(float4*)&rb[4] = *(const float4*)&sKt[d * ATT_KT + tx * 8 + 4];
            #pragma unroll
            for (int i = 0; i < 4; i++)
                #pragma unroll
                for (int j = 0; j < 8; j++)
                    acc[i][j] = fmaf(ra[i], rb[j], acc[i][j]);
        }
        #pragma unroll
        for (int i = 0; i < 4; i++)
            #pragma unroll
            for (int j = 0; j < 8; j++)
                sS[(ty * 4 + i) * 65 + tx * 8 + j] = acc[i][j] * 0.125f;
        __syncthreads();

        if (tid < 128) {
            #pragma unroll 1
            for (int kk = 0; kk < ATT_KT; kk++) {
                float s = sS[tid * 65 + kk];
                if (s > curMin) {
                    sTV[tid * 33 + curPos] = s;
                    sTI[tid * 33 + curPos] = kt * ATT_KT + kk;
                    float mn = sTV[tid * 33];
                    int   mp = 0;
                    #pragma unroll
                    for (int j = 1; j < TOPKk; j++) {
                        float v = sTV[tid * 33 + j];
                        if (v < mn) { mn = v; mp = j; }
                    }
                    curMin = mn; curPos = mp;
                }
            }
        }
        __syncthreads();
    }

    const int warp = tid >> 5;
    const int lane = tid & 31;
    for (int qi = warp; qi < ATT_QT; qi += 8) {
        float v  = sTV[qi * 33 + lane];
        int   ki = sTI[qi * 33 + lane];

        float mx = v;
        #pragma unroll
        for (int o = 16; o; o >>= 1) mx = fmaxf(mx, __shfl_xor_sync(0xffffffffu, mx, o));
        float e = expf(v - mx);
        float se = e;
        #pragma unroll
        for (int o = 16; o; o >>= 1) se += __shfl_xor_sync(0xffffffffu, se, o);
        float w = e / se;

        float a0 = 0.f, a1 = 0.f;
        #pragma unroll
        for (int j = 0; j < TOPKk; j++) {
            float wj = __shfl_sync(0xffffffffu, w, j);
            int   kj = __shfl_sync(0xffffffffu, ki, j);
            const float* vr = gv + ((size_t)(b * Ll + kj)) * Ee + h * DHh;
            a0 = fmaf(wj, vr[lane],      a0);
            a1 = fmaf(wj, vr[lane + 32], a1);
        }
        float* op = gao + ((size_t)(b * Ll + l0 + qi)) * Ee + h * DHh;
        op[lane]      = a0;
        op[lane + 32] = a1;
    }
}

// ============================================================
extern "C" void kernel_launch(void* const* d_in, const int* in_sizes, int n_in,
                              void* d_out, int out_size)
{
    const float* Q  = (const float*)d_in[0];
    const float* K_ = (const float*)d_in[1];
    const float* V  = (const float*)d_in[2];
    const float* Wq = (const float*)d_in[3];
    const float* bq = (const float*)d_in[4];
    const float* Wk = (const float*)d_in[5];
    const float* bk = (const float*)d_in[6];
    const float* Wv = (const float*)d_in[7];
    const float* bv = (const float*)d_in[8];
    const float* Wo = (const float*)d_in[9];
    const float* bo = (const float*)d_in[10];
    float* out = (float*)d_out;

    float *gq, *gk, *gv, *gao;
    cudaGetSymbolAddress((void**)&gq,  g_q);
    cudaGetSymbolAddress((void**)&gk,  g_k);
    cudaGetSymbolAddress((void**)&gv,  g_v);
    cudaGetSymbolAddress((void**)&gao, g_ao);
    __nv_bfloat16 *xs1, *xs2, *ws1, *ws2;
    cudaGetSymbolAddress((void**)&xs1, g_xs1);
    cudaGetSymbolAddress((void**)&xs2, g_xs2);
    cudaGetSymbolAddress((void**)&ws1, g_ws1);
    cudaGetSymbolAddress((void**)&ws2, g_ws2);

    const int M = Bb * Ll;
    const int N = Ee;
    const int K = Ee;

    dim3 gblock(256);
    dim3 ggrid(N / GBN, M / GBM);

    // q, k projections: scalar fp32 (bit-identical)
    gemm_nt_bias<<<ggrid, gblock>>>(Q,  Wq, bq, gq, M, N, K);
    gemm_nt_bias<<<ggrid, gblock>>>(K_, Wk, bk, gk, M, N, K);

    // v projection: tensor-core bf16x2, double-buffered
    split2_kernel<<<(M*K + 255)/256, 256>>>(V,  xs1, xs2, M*K);
    split2_kernel<<<(N*K + 255)/256, 256>>>(Wv, ws1, ws2, N*K);
    cudaFuncSetAttribute(gemm_bf16x2_mma,
                         cudaFuncAttributeMaxDynamicSharedMemorySize, TG_SMEM);
    dim3 tgrid(N / 128, M / 128);
    gemm_bf16x2_mma<<<tgrid, 256, TG_SMEM>>>(xs1, xs2, ws1, ws2, bv, gv);

    // sparse top-k attention
    size_t attSmem = ATT_SMEM_FLOATS * sizeof(float);
    cudaFuncSetAttribute(attn_topk_kernel,
                         cudaFuncAttributeMaxDynamicSharedMemorySize, (int)attSmem);
    dim3 agrid(Ll / ATT_QT, Bb * Hh);
    attn_topk_kernel<<<agrid, ATT_THREADS, attSmem>>>(gq, gk, gv, gao);

    // output projection: tensor-core bf16x2
    split2_kernel<<<(M*K + 255)/256, 256>>>(gao, xs1, xs2, M*K);
    split2_kernel<<<(N*K + 255)/256, 256>>>(Wo,  ws1, ws2, N*K);
    gemm_bf16x2_mma<<<tgrid, 256, TG_SMEM>>>(xs1, xs2, ws1, ws2, bo, out);
}